// round 1
// baseline (speedup 1.0000x reference)
#include <cuda_runtime.h>
#include <math.h>

// Problem constants (fixed by the dataset)
#define N_NODES 25000
#define N_EDGES 400000
#define IN_FEATS 256
#define HID 64
#define HEADS 8
#define HF (HID*HEADS)      // 512
#define CLASSES 32

// ---------------- scratch (static __device__ — no allocs allowed) ----------
__device__ float g_z [N_NODES * HF];   // GEMM output of current layer
__device__ float g_x1[N_NODES * HF];   // layer-1 aggregated output
__device__ float g_x2[N_NODES * HF];   // layer-2 aggregated output
__device__ float g_el[N_NODES * HEADS];
__device__ float g_er[N_NODES * HEADS];
__device__ int   g_rowptr[N_NODES + 1];

// ---------------- CSR row offsets from sorted dst --------------------------
__global__ void rowptr_kernel(const int* __restrict__ dst, int* __restrict__ rowptr,
                              int E, int N) {
    int v = blockIdx.x * blockDim.x + threadIdx.x;
    if (v > N) return;
    int lo = 0, hi = E;                 // first index with dst[i] >= v
    while (lo < hi) {
        int mid = (lo + hi) >> 1;
        if (dst[mid] < v) lo = mid + 1; else hi = mid;
    }
    rowptr[v] = lo;
}

// ---------------- SIMT fp32 GEMM: C[M,N] = A[M,K] * B[N,K]^T ---------------
#define BM 128
#define BN 64
#define BKK 16
#define TM 8
#define TN 4
__global__ void __launch_bounds__(256)
gemm_nt_kernel(const float* __restrict__ A, const float* __restrict__ B,
               float* __restrict__ C, int M, int N, int K) {
    __shared__ float As[BKK][BM + 4];
    __shared__ float Bs[BKK][BN + 4];
    int tid = threadIdx.x;
    int m0 = blockIdx.y * BM;
    int n0 = blockIdx.x * BN;
    int tx = tid & 15;          // 0..15 -> n direction (TN=4 -> 64)
    int ty = tid >> 4;          // 0..15 -> m direction (TM=8 -> 128)
    int lrow = tid >> 2;        // 0..63
    int lcol = (tid & 3) * 4;   // 0,4,8,12

    float acc[TM][TN];
#pragma unroll
    for (int i = 0; i < TM; ++i)
#pragma unroll
        for (int j = 0; j < TN; ++j) acc[i][j] = 0.f;

    for (int k0 = 0; k0 < K; k0 += BKK) {
        // A tile: 128x16, two float4 per thread
#pragma unroll
        for (int r = 0; r < 2; ++r) {
            int m = m0 + lrow + r * 64;
            float4 v = make_float4(0.f, 0.f, 0.f, 0.f);
            if (m < M) v = *(const float4*)(A + (size_t)m * K + k0 + lcol);
            As[lcol + 0][lrow + r * 64] = v.x;
            As[lcol + 1][lrow + r * 64] = v.y;
            As[lcol + 2][lrow + r * 64] = v.z;
            As[lcol + 3][lrow + r * 64] = v.w;
        }
        // B tile: 64x16, one float4 per thread
        {
            int n = n0 + lrow;
            float4 v = make_float4(0.f, 0.f, 0.f, 0.f);
            if (n < N) v = *(const float4*)(B + (size_t)n * K + k0 + lcol);
            Bs[lcol + 0][lrow] = v.x;
            Bs[lcol + 1][lrow] = v.y;
            Bs[lcol + 2][lrow] = v.z;
            Bs[lcol + 3][lrow] = v.w;
        }
        __syncthreads();
#pragma unroll
        for (int kk = 0; kk < BKK; ++kk) {
            float ra[TM], rb[TN];
#pragma unroll
            for (int i = 0; i < TM; ++i) ra[i] = As[kk][ty * TM + i];
#pragma unroll
            for (int j = 0; j < TN; ++j) rb[j] = Bs[kk][tx * TN + j];
#pragma unroll
            for (int i = 0; i < TM; ++i)
#pragma unroll
                for (int j = 0; j < TN; ++j) acc[i][j] += ra[i] * rb[j];
        }
        __syncthreads();
    }
#pragma unroll
    for (int i = 0; i < TM; ++i) {
        int m = m0 + ty * TM + i;
        if (m >= M) continue;
#pragma unroll
        for (int j = 0; j < TN; ++j) {
            int n = n0 + tx * TN + j;
            if (n < N) C[(size_t)m * N + n] = acc[i][j];
        }
    }
}

// ---------------- attention scores el/er per (node, head) ------------------
template <int H, int F>
__global__ void scores_kernel(const float* __restrict__ z,
                              const float* __restrict__ al,
                              const float* __restrict__ ar,
                              float* __restrict__ el, float* __restrict__ er,
                              int N) {
    int idx = blockIdx.x * blockDim.x + threadIdx.x;   // n*H + h
    if (idx >= N * H) return;
    int h = idx % H;
    const float* zr = z + (size_t)idx * F;             // (n*H+h)*F contiguous
    const float* alr = al + h * F;
    const float* arr = ar + h * F;
    float sl = 0.f, sr = 0.f;
#pragma unroll 4
    for (int f = 0; f < F; f += 4) {
        float4 zv = *(const float4*)(zr + f);
        float4 av = *(const float4*)(alr + f);
        float4 bv = *(const float4*)(arr + f);
        sl += zv.x * av.x + zv.y * av.y + zv.z * av.z + zv.w * av.w;
        sr += zv.x * bv.x + zv.y * bv.y + zv.z * bv.z + zv.w * bv.w;
    }
    el[idx] = sl;
    er[idx] = sr;
}

// ---------------- per-node edge softmax + aggregation (one warp per node) --
// dst is sorted -> CSR rowptr gives each node's incoming-edge range.
template <int H, int F, bool ELU>
__global__ void aggregate_kernel(const float* __restrict__ z,
                                 const int* __restrict__ src,
                                 const int* __restrict__ rowptr,
                                 const float* __restrict__ el,
                                 const float* __restrict__ er,
                                 float* __restrict__ out, int N) {
    constexpr int HFv = H * F;
    constexpr int KF = HFv / 32;       // features per lane
    int warp_id = (blockIdx.x * blockDim.x + threadIdx.x) >> 5;
    if (warp_id >= N) return;
    int lane = threadIdx.x & 31;
    int v = warp_id;
    int start = rowptr[v];
    int end   = rowptr[v + 1];

    int h = lane % H;                  // this lane's head (replicated 32/H x)
    float erv = er[(size_t)v * H + h];

    // pass 1: per-head max of leaky_relu(el[src]+er[v])
    float m = -INFINITY;
    for (int i = start + lane / H; i < end; i += 32 / H) {
        int s = src[i];
        float e = el[(size_t)s * H + h] + erv;
        e = e > 0.f ? e : 0.2f * e;
        m = fmaxf(m, e);
    }
#pragma unroll
    for (int off = H; off < 32; off <<= 1)
        m = fmaxf(m, __shfl_xor_sync(0xFFFFFFFFu, m, off));

    // pass 2: weighted accumulation + denominator
    float denom = 0.f;
    float acc[KF];
#pragma unroll
    for (int k = 0; k < KF; ++k) acc[k] = 0.f;

    for (int i = start; i < end; ++i) {
        int s = __shfl_sync(0xFFFFFFFFu, lane == 0 ? src[i] : 0, 0);
        float e = el[(size_t)s * H + h] + erv;
        e = e > 0.f ? e : 0.2f * e;
        float w = __expf(e - m);
        denom += w;
        float wv[H];
#pragma unroll
        for (int hh = 0; hh < H; ++hh) wv[hh] = __shfl_sync(0xFFFFFFFFu, w, hh);
        const float* zr = z + (size_t)s * HFv;
#pragma unroll
        for (int k = 0; k < KF; ++k)
            acc[k] += wv[(k * 32) / F] * zr[k * 32 + lane];
    }

    float denv[H];
#pragma unroll
    for (int hh = 0; hh < H; ++hh) denv[hh] = __shfl_sync(0xFFFFFFFFu, denom, hh);

    float* outr = out + (size_t)v * HFv;
#pragma unroll
    for (int k = 0; k < KF; ++k) {
        float d = denv[(k * 32) / F];
        float val = (end > start) ? acc[k] / d : 0.f;
        if (ELU) val = val > 0.f ? val : (__expf(val) - 1.f);
        outr[k * 32 + lane] = val;
    }
}

// ---------------- launch --------------------------------------------------
extern "C" void kernel_launch(void* const* d_in, const int* in_sizes, int n_in,
                              void* d_out, int out_size) {
    const float* h   = (const float*)d_in[0];
    const int*   src = (const int*)  d_in[1];
    const int*   dst = (const int*)  d_in[2];
    const float* W1  = (const float*)d_in[3];
    const float* al1 = (const float*)d_in[4];
    const float* ar1 = (const float*)d_in[5];
    const float* W2  = (const float*)d_in[6];
    const float* al2 = (const float*)d_in[7];
    const float* ar2 = (const float*)d_in[8];
    const float* W3  = (const float*)d_in[9];
    const float* al3 = (const float*)d_in[10];
    const float* ar3 = (const float*)d_in[11];
    float* out = (float*)d_out;

    const int N = N_NODES, E = N_EDGES;

    float *z, *x1, *x2, *el, *er;
    int* rowptr;
    cudaGetSymbolAddress((void**)&z,  g_z);
    cudaGetSymbolAddress((void**)&x1, g_x1);
    cudaGetSymbolAddress((void**)&x2, g_x2);
    cudaGetSymbolAddress((void**)&el, g_el);
    cudaGetSymbolAddress((void**)&er, g_er);
    cudaGetSymbolAddress((void**)&rowptr, g_rowptr);

    // CSR row offsets from sorted dst
    rowptr_kernel<<<(N + 1 + 255) / 256, 256>>>(dst, rowptr, E, N);

    dim3 gemm_block(256);
    int agg_blocks = (N * 32 + 255) / 256;   // one warp per node, 8 warps/block

    // ---- layer 1: [N,256] x [512,256]^T -> z[N,512]
    {
        dim3 grid((HF + BN - 1) / BN, (N + BM - 1) / BM);
        gemm_nt_kernel<<<grid, gemm_block>>>(h, W1, z, N, HF, IN_FEATS);
        scores_kernel<HEADS, HID><<<(N * HEADS + 255) / 256, 256>>>(z, al1, ar1, el, er, N);
        aggregate_kernel<HEADS, HID, true><<<agg_blocks, 256>>>(z, src, rowptr, el, er, x1, N);
    }
    // ---- layer 2: [N,512] x [512,512]^T -> z[N,512]
    {
        dim3 grid((HF + BN - 1) / BN, (N + BM - 1) / BM);
        gemm_nt_kernel<<<grid, gemm_block>>>(x1, W2, z, N, HF, HF);
        scores_kernel<HEADS, HID><<<(N * HEADS + 255) / 256, 256>>>(z, al2, ar2, el, er, N);
        aggregate_kernel<HEADS, HID, true><<<agg_blocks, 256>>>(z, src, rowptr, el, er, x2, N);
    }
    // ---- layer 3: [N,512] x [32,512]^T -> z[N,32], H=1, F=32, no ELU
    {
        dim3 grid((CLASSES + BN - 1) / BN, (N + BM - 1) / BM);
        gemm_nt_kernel<<<grid, gemm_block>>>(x2, W3, z, N, CLASSES, HF);
        scores_kernel<1, CLASSES><<<(N + 255) / 256, 256>>>(z, al3, ar3, el, er, N);
        aggregate_kernel<1, CLASSES, false><<<agg_blocks, 256>>>(z, src, rowptr, el, er, out, N);
    }
}

// round 2
// speedup vs baseline: 1.0486x; 1.0486x over previous
#include <cuda_runtime.h>
#include <math.h>

typedef unsigned long long ull;

// Problem constants (fixed by the dataset)
#define N_NODES 25000
#define N_EDGES 400000
#define IN_FEATS 256
#define HID 64
#define HEADS 8
#define HF (HID*HEADS)      // 512
#define CLASSES 32

// ---------------- scratch (static __device__ — no allocs allowed) ----------
__device__ float g_z [N_NODES * HF];   // GEMM output of current layer
__device__ float g_x1[N_NODES * HF];   // layer-1 aggregated output
__device__ float g_x2[N_NODES * HF];   // layer-2 aggregated output
__device__ float g_el[N_NODES * HEADS];
__device__ float g_er[N_NODES * HEADS];
__device__ int   g_rowptr[N_NODES + 1];

// packed f32x2 helpers (sm_103a dual-FMA pipe)
__device__ __forceinline__ ull dup_f32x2(float b) {
    ull r;
    asm("mov.b64 %0, {%1, %1};" : "=l"(r) : "r"(__float_as_uint(b)));
    return r;
}
__device__ __forceinline__ void ffma2(ull& d, ull a, ull b) {
    asm("fma.rn.f32x2 %0, %1, %2, %0;" : "+l"(d) : "l"(a), "l"(b));
}
__device__ __forceinline__ float2 unpack_f32x2(ull v) {
    float2 p;
    asm("mov.b64 {%0, %1}, %2;" : "=f"(p.x), "=f"(p.y) : "l"(v));
    return p;
}

// ---------------- CSR row offsets from sorted dst --------------------------
__global__ void rowptr_kernel(const int* __restrict__ dst, int* __restrict__ rowptr,
                              int E, int N) {
    int v = blockIdx.x * blockDim.x + threadIdx.x;
    if (v > N) return;
    int lo = 0, hi = E;                 // first index with dst[i] >= v
    while (lo < hi) {
        int mid = (lo + hi) >> 1;
        if (dst[mid] < v) lo = mid + 1; else hi = mid;
    }
    rowptr[v] = lo;
}

// ---------------- f32x2 GEMM: C[M,N] = A[M,K] * B[N,K]^T -------------------
// 256 threads, BM=128, BN=128, BK=16. Thread (tx,ty), tx=tid&15, ty=tid>>4.
// Thread computes rows m0+ty*8 .. +7 (4 M-pairs) x cols n0+tx+16*j (j=0..7).
// Accumulators are f32x2 pairs along M -> fma.rn.f32x2 (2x fp32 throughput).
#define BM 128
#define BN 128
#define BKK 16
__global__ void __launch_bounds__(256, 2)
gemm2_nt_kernel(const float* __restrict__ A, const float* __restrict__ B,
                float* __restrict__ C, int M, int N, int K) {
    __shared__ float As[BKK][BM + 2];
    __shared__ float Bs[BKK][BN + 2];
    int tid = threadIdx.x;
    int m0 = blockIdx.y * BM;
    int n0 = blockIdx.x * BN;
    int tx = tid & 15;
    int ty = tid >> 4;
    int lrow = tid >> 2;        // 0..63
    int lcol = (tid & 3) * 4;   // 0,4,8,12

    ull acc[8][4];              // [j (N dir)][i2 (M pair)]
#pragma unroll
    for (int j = 0; j < 8; ++j)
#pragma unroll
        for (int i = 0; i < 4; ++i) acc[j][i] = 0ull;

    for (int k0 = 0; k0 < K; k0 += BKK) {
        // A tile 128x16 and B tile 128x16, transposed into smem
#pragma unroll
        for (int r = 0; r < 2; ++r) {
            int m = m0 + lrow + r * 64;
            float4 va = make_float4(0.f, 0.f, 0.f, 0.f);
            if (m < M) va = *(const float4*)(A + (size_t)m * K + k0 + lcol);
            As[lcol + 0][lrow + r * 64] = va.x;
            As[lcol + 1][lrow + r * 64] = va.y;
            As[lcol + 2][lrow + r * 64] = va.z;
            As[lcol + 3][lrow + r * 64] = va.w;

            int n = n0 + lrow + r * 64;
            float4 vb = make_float4(0.f, 0.f, 0.f, 0.f);
            if (n < N) vb = *(const float4*)(B + (size_t)n * K + k0 + lcol);
            Bs[lcol + 0][lrow + r * 64] = vb.x;
            Bs[lcol + 1][lrow + r * 64] = vb.y;
            Bs[lcol + 2][lrow + r * 64] = vb.z;
            Bs[lcol + 3][lrow + r * 64] = vb.w;
        }
        __syncthreads();
#pragma unroll
        for (int kk = 0; kk < BKK; ++kk) {
            ull ra[4];
#pragma unroll
            for (int i = 0; i < 4; ++i)
                ra[i] = *(const ull*)&As[kk][ty * 8 + 2 * i];   // LDS.64, broadcast
#pragma unroll
            for (int j = 0; j < 8; ++j) {
                ull b2 = dup_f32x2(Bs[kk][tx + 16 * j]);        // conflict-free LDS.32
#pragma unroll
                for (int i = 0; i < 4; ++i)
                    ffma2(acc[j][i], ra[i], b2);
            }
        }
        __syncthreads();
    }
    // epilogue
#pragma unroll
    for (int j = 0; j < 8; ++j) {
        int n = n0 + tx + 16 * j;
        if (n >= N) continue;
#pragma unroll
        for (int i = 0; i < 4; ++i) {
            float2 p = unpack_f32x2(acc[j][i]);
            int m = m0 + ty * 8 + 2 * i;
            if (m < M)     C[(size_t)m * N + n]       = p.x;
            if (m + 1 < M) C[(size_t)(m + 1) * N + n] = p.y;
        }
    }
}

// ---------------- attention scores el/er per (node, head) ------------------
template <int H, int F>
__global__ void scores_kernel(const float* __restrict__ z,
                              const float* __restrict__ al,
                              const float* __restrict__ ar,
                              float* __restrict__ el, float* __restrict__ er,
                              int N) {
    int idx = blockIdx.x * blockDim.x + threadIdx.x;   // n*H + h
    if (idx >= N * H) return;
    int h = idx % H;
    const float* zr = z + (size_t)idx * F;             // (n*H+h)*F contiguous
    const float* alr = al + h * F;
    const float* arr = ar + h * F;
    float sl = 0.f, sr = 0.f;
#pragma unroll 4
    for (int f = 0; f < F; f += 4) {
        float4 zv = *(const float4*)(zr + f);
        float4 av = *(const float4*)(alr + f);
        float4 bv = *(const float4*)(arr + f);
        sl += zv.x * av.x + zv.y * av.y + zv.z * av.z + zv.w * av.w;
        sr += zv.x * bv.x + zv.y * bv.y + zv.z * bv.z + zv.w * bv.w;
    }
    el[idx] = sl;
    er[idx] = sr;
}

// ---------------- per-node edge softmax + aggregation (one warp per node) --
// dst is sorted -> CSR rowptr gives each node's incoming-edge range.
// For HF>=64 we use the packed f32x2 path: lane owns a contiguous float2,
// warp covers 64 consecutive features per k (head index == k for F=64,H=8).
template <int H, int F, bool ELU>
__global__ void aggregate_kernel(const float* __restrict__ z,
                                 const int* __restrict__ src,
                                 const int* __restrict__ rowptr,
                                 const float* __restrict__ el,
                                 const float* __restrict__ er,
                                 float* __restrict__ out, int N) {
    constexpr int HFv = H * F;
    int warp_id = (blockIdx.x * blockDim.x + threadIdx.x) >> 5;
    if (warp_id >= N) return;
    int lane = threadIdx.x & 31;
    int v = warp_id;
    int start = rowptr[v];
    int end   = rowptr[v + 1];

    int h = lane % H;                  // this lane's head (replicated 32/H x)
    float erv = er[(size_t)v * H + h];

    // pass 1: per-head max of leaky_relu(el[src]+er[v])
    float m = -INFINITY;
    for (int i = start + lane / H; i < end; i += 32 / H) {
        int s = src[i];
        float e = el[(size_t)s * H + h] + erv;
        e = e > 0.f ? e : 0.2f * e;
        m = fmaxf(m, e);
    }
#pragma unroll
    for (int off = H; off < 32; off <<= 1)
        m = fmaxf(m, __shfl_xor_sync(0xFFFFFFFFu, m, off));

    // pass 2: weighted accumulation + denominator
    float denom = 0.f;

    if constexpr (HFv >= 64 && F == 64 && H == 8) {
        constexpr int KP = HFv / 64;   // 8 pair-chunks of 64 floats
        ull acc[KP];
#pragma unroll
        for (int k = 0; k < KP; ++k) acc[k] = 0ull;

        for (int i = start; i < end; ++i) {
            int s = __shfl_sync(0xFFFFFFFFu, lane == 0 ? src[i] : 0, 0);
            float e = el[(size_t)s * H + h] + erv;
            e = e > 0.f ? e : 0.2f * e;
            float w = __expf(e - m);
            denom += w;
            const float* zr = z + (size_t)s * HFv;
#pragma unroll
            for (int k = 0; k < KP; ++k) {
                float wk = __shfl_sync(0xFFFFFFFFu, w, k);   // head of chunk k is k
                ull zv = *(const ull*)(zr + k * 64 + lane * 2);  // LDG.64 coalesced
                ffma2(acc[k], zv, dup_f32x2(wk));
            }
        }

        float* outr = out + (size_t)v * HFv;
#pragma unroll
        for (int k = 0; k < KP; ++k) {
            float d = __shfl_sync(0xFFFFFFFFu, denom, k);
            float2 p = unpack_f32x2(acc[k]);
            float vx = (end > start) ? p.x / d : 0.f;
            float vy = (end > start) ? p.y / d : 0.f;
            if (ELU) {
                vx = vx > 0.f ? vx : (__expf(vx) - 1.f);
                vy = vy > 0.f ? vy : (__expf(vy) - 1.f);
            }
            *(float2*)(outr + k * 64 + lane * 2) = make_float2(vx, vy);
        }
    } else {
        constexpr int KF = HFv / 32;       // features per lane (scalar path)
        float acc[KF];
#pragma unroll
        for (int k = 0; k < KF; ++k) acc[k] = 0.f;

        for (int i = start; i < end; ++i) {
            int s = __shfl_sync(0xFFFFFFFFu, lane == 0 ? src[i] : 0, 0);
            float e = el[(size_t)s * H + h] + erv;
            e = e > 0.f ? e : 0.2f * e;
            float w = __expf(e - m);
            denom += w;
            float wv[H];
#pragma unroll
            for (int hh = 0; hh < H; ++hh) wv[hh] = __shfl_sync(0xFFFFFFFFu, w, hh);
            const float* zr = z + (size_t)s * HFv;
#pragma unroll
            for (int k = 0; k < KF; ++k)
                acc[k] += wv[(k * 32) / F] * zr[k * 32 + lane];
        }

        float denv[H];
#pragma unroll
        for (int hh = 0; hh < H; ++hh) denv[hh] = __shfl_sync(0xFFFFFFFFu, denom, hh);

        float* outr = out + (size_t)v * HFv;
#pragma unroll
        for (int k = 0; k < KF; ++k) {
            float d = denv[(k * 32) / F];
            float val = (end > start) ? acc[k] / d : 0.f;
            if (ELU) val = val > 0.f ? val : (__expf(val) - 1.f);
            outr[k * 32 + lane] = val;
        }
    }
}

// ---------------- launch --------------------------------------------------
extern "C" void kernel_launch(void* const* d_in, const int* in_sizes, int n_in,
                              void* d_out, int out_size) {
    const float* h   = (const float*)d_in[0];
    const int*   src = (const int*)  d_in[1];
    const int*   dst = (const int*)  d_in[2];
    const float* W1  = (const float*)d_in[3];
    const float* al1 = (const float*)d_in[4];
    const float* ar1 = (const float*)d_in[5];
    const float* W2  = (const float*)d_in[6];
    const float* al2 = (const float*)d_in[7];
    const float* ar2 = (const float*)d_in[8];
    const float* W3  = (const float*)d_in[9];
    const float* al3 = (const float*)d_in[10];
    const float* ar3 = (const float*)d_in[11];
    float* out = (float*)d_out;

    const int N = N_NODES, E = N_EDGES;

    float *z, *x1, *x2, *el, *er;
    int* rowptr;
    cudaGetSymbolAddress((void**)&z,  g_z);
    cudaGetSymbolAddress((void**)&x1, g_x1);
    cudaGetSymbolAddress((void**)&x2, g_x2);
    cudaGetSymbolAddress((void**)&el, g_el);
    cudaGetSymbolAddress((void**)&er, g_er);
    cudaGetSymbolAddress((void**)&rowptr, g_rowptr);

    // CSR row offsets from sorted dst
    rowptr_kernel<<<(N + 1 + 255) / 256, 256>>>(dst, rowptr, E, N);

    int agg_blocks = (N * 32 + 255) / 256;   // one warp per node, 8 warps/block

    // ---- layer 1: [N,256] x [512,256]^T -> z[N,512]
    {
        dim3 grid((HF + BN - 1) / BN, (N + BM - 1) / BM);
        gemm2_nt_kernel<<<grid, 256>>>(h, W1, z, N, HF, IN_FEATS);
        scores_kernel<HEADS, HID><<<(N * HEADS + 255) / 256, 256>>>(z, al1, ar1, el, er, N);
        aggregate_kernel<HEADS, HID, true><<<agg_blocks, 256>>>(z, src, rowptr, el, er, x1, N);
    }
    // ---- layer 2: [N,512] x [512,512]^T -> z[N,512]
    {
        dim3 grid((HF + BN - 1) / BN, (N + BM - 1) / BM);
        gemm2_nt_kernel<<<grid, 256>>>(x1, W2, z, N, HF, HF);
        scores_kernel<HEADS, HID><<<(N * HEADS + 255) / 256, 256>>>(z, al2, ar2, el, er, N);
        aggregate_kernel<HEADS, HID, true><<<agg_blocks, 256>>>(z, src, rowptr, el, er, x2, N);
    }
    // ---- layer 3: [N,512] x [32,512]^T -> z[N,32], H=1, F=32, no ELU
    {
        dim3 grid((CLASSES + BN - 1) / BN, (N + BM - 1) / BM);
        gemm2_nt_kernel<<<grid, 256>>>(x2, W3, z, N, CLASSES, HF);
        scores_kernel<1, CLASSES><<<(N + 255) / 256, 256>>>(z, al3, ar3, el, er, N);
        aggregate_kernel<1, CLASSES, false><<<agg_blocks, 256>>>(z, src, rowptr, el, er, out, N);
    }
}

// round 4
// speedup vs baseline: 1.8480x; 1.7623x over previous
#include <cuda_runtime.h>
#include <cuda_bf16.h>
#include <cstdint>
#include <math.h>

typedef unsigned long long ull;

// Problem constants (fixed by the dataset)
#define N_NODES 25000
#define N_EDGES 400000
#define IN_FEATS 256
#define HID 64
#define HEADS 8
#define HF (HID*HEADS)      // 512
#define CLASSES 32

// ---------------- scratch (static __device__ — no allocs allowed) ----------
__device__ float g_z [N_NODES * HF];
__device__ float g_x1[N_NODES * HF];
__device__ float g_x2[N_NODES * HF];
__device__ float g_el[N_NODES * HEADS];
__device__ float g_er[N_NODES * HEADS];
__device__ int   g_rowptr[N_NODES + 1];

// ---------------- small PTX helpers ---------------------------------------
__device__ __forceinline__ uint32_t smem_u32(const void* p) {
    uint32_t a;
    asm("{ .reg .u64 t; cvta.to.shared.u64 t, %1; cvt.u32.u64 %0, t; }" : "=r"(a) : "l"(p));
    return a;
}
__device__ __forceinline__ void ldm_x4(uint32_t* r, uint32_t addr) {
    asm volatile("ldmatrix.sync.aligned.m8n8.x4.shared.b16 {%0,%1,%2,%3}, [%4];"
        : "=r"(r[0]), "=r"(r[1]), "=r"(r[2]), "=r"(r[3]) : "r"(addr));
}
__device__ __forceinline__ void mma_bf16(float* c, const uint32_t* a, const uint32_t* b) {
    asm volatile(
        "mma.sync.aligned.m16n8k16.row.col.f32.bf16.bf16.f32 "
        "{%0,%1,%2,%3}, {%4,%5,%6,%7}, {%8,%9}, {%0,%1,%2,%3};"
        : "+f"(c[0]), "+f"(c[1]), "+f"(c[2]), "+f"(c[3])
        : "r"(a[0]), "r"(a[1]), "r"(a[2]), "r"(a[3]), "r"(b[0]), "r"(b[1]));
}

// packed f32x2 helpers (aggregate kernel)
__device__ __forceinline__ ull dup_f32x2(float b) {
    ull r; asm("mov.b64 %0, {%1, %1};" : "=l"(r) : "r"(__float_as_uint(b))); return r;
}
__device__ __forceinline__ void ffma2(ull& d, ull a, ull b) {
    asm("fma.rn.f32x2 %0, %1, %2, %0;" : "+l"(d) : "l"(a), "l"(b));
}
__device__ __forceinline__ float2 unpack_f32x2(ull v) {
    float2 p; asm("mov.b64 {%0, %1}, %2;" : "=f"(p.x), "=f"(p.y) : "l"(v)); return p;
}

// ---------------- CSR row offsets from sorted dst --------------------------
__global__ void rowptr_kernel(const int* __restrict__ dst, int* __restrict__ rowptr,
                              int E, int N) {
    int v = blockIdx.x * blockDim.x + threadIdx.x;
    if (v > N) return;
    int lo = 0, hi = E;
    while (lo < hi) {
        int mid = (lo + hi) >> 1;
        if (dst[mid] < v) lo = mid + 1; else hi = mid;
    }
    rowptr[v] = lo;
}

// =================== bf16-split mma.sync GEMM: C = A[M,K]*B[N,K]^T =========
// a = hi + res, both bf16.  C += hi*hi + hi*res + res*hi  (error ~2^-17).
// BM=128, BK=32 (bf16 elems). 8 warps: WM x WN grid, warp tile (BM/WM)x(BN/WN).
template <int BN, int WM, int WN>
__global__ void __launch_bounds__(256, 2)
gemm_mma_kernel(const float* __restrict__ A, const float* __restrict__ B,
                float* __restrict__ C, int M, int N, int K) {
    constexpr int BM = 128, BK = 32, ROWP = 40;   // 40 bf16 = 80B row stride
    constexpr int WTM = BM / WM;
    constexpr int WTN = BN / WN;
    constexpr int MSUB = WTM / 16;
    constexpr int NSUB = WTN / 8;
    constexpr int BQ = (BN * BK / 4) / 256;       // float4 B loads per thread

    __shared__ __align__(16) __nv_bfloat16 Ah[BM * ROWP];
    __shared__ __align__(16) __nv_bfloat16 Ar[BM * ROWP];
    __shared__ __align__(16) __nv_bfloat16 Bh[BN * ROWP];
    __shared__ __align__(16) __nv_bfloat16 Br[BN * ROWP];

    const int tid = threadIdx.x, wid = tid >> 5, lane = tid & 31;
    const int m0 = blockIdx.y * BM, n0 = blockIdx.x * BN;
    const int wm = wid % WM, wn = wid / WM;
    const int wmb = wm * WTM, wnb = wn * WTN;

    float acc[MSUB][NSUB][4];
#pragma unroll
    for (int i = 0; i < MSUB; ++i)
#pragma unroll
        for (int j = 0; j < NSUB; ++j)
#pragma unroll
            for (int q = 0; q < 4; ++q) acc[i][j][q] = 0.f;

    float4 aS[4], bS[BQ > 0 ? BQ : 1];

    auto loadA = [&](int c) {
        const int k0 = c * BK;
#pragma unroll
        for (int it = 0; it < 4; ++it) {
            int idx = tid + it * 256;
            int row = idx >> 3, col = (idx & 7) * 4;
            int m = m0 + row;
            aS[it] = (m < M) ? *(const float4*)(A + (size_t)m * K + k0 + col)
                             : make_float4(0.f, 0.f, 0.f, 0.f);
        }
    };
    auto loadB = [&](int c) {
        const int k0 = c * BK;
#pragma unroll
        for (int it = 0; it < BQ; ++it) {
            int idx = tid + it * 256;
            int row = idx >> 3, col = (idx & 7) * 4;
            bS[it] = *(const float4*)(B + (size_t)(n0 + row) * K + k0 + col);
        }
    };
    auto cvt_store = [&](__nv_bfloat16* Sh, __nv_bfloat16* Sr, int idx, float4 v) {
        int row = idx >> 3, col = (idx & 7) * 4;
        float hx = __bfloat162float(__float2bfloat16_rn(v.x));
        float hy = __bfloat162float(__float2bfloat16_rn(v.y));
        float hz = __bfloat162float(__float2bfloat16_rn(v.z));
        float hw = __bfloat162float(__float2bfloat16_rn(v.w));
        __nv_bfloat162 h01 = __floats2bfloat162_rn(hx, hy);
        __nv_bfloat162 h23 = __floats2bfloat162_rn(hz, hw);
        __nv_bfloat162 r01 = __floats2bfloat162_rn(v.x - hx, v.y - hy);
        __nv_bfloat162 r23 = __floats2bfloat162_rn(v.z - hz, v.w - hw);
        *reinterpret_cast<__nv_bfloat162*>(&Sh[row * ROWP + col])     = h01;
        *reinterpret_cast<__nv_bfloat162*>(&Sh[row * ROWP + col + 2]) = h23;
        *reinterpret_cast<__nv_bfloat162*>(&Sr[row * ROWP + col])     = r01;
        *reinterpret_cast<__nv_bfloat162*>(&Sr[row * ROWP + col + 2]) = r23;
    };
    auto storeA = [&]() {
#pragma unroll
        for (int it = 0; it < 4; ++it) cvt_store(Ah, Ar, tid + it * 256, aS[it]);
    };
    auto storeB = [&]() {
#pragma unroll
        for (int it = 0; it < BQ; ++it) cvt_store(Bh, Br, tid + it * 256, bS[it]);
    };

    const uint32_t ahBase = smem_u32(Ah), arBase = smem_u32(Ar);
    const uint32_t bhBase = smem_u32(Bh), brBase = smem_u32(Br);

    const int NCH = K / BK;
    loadA(0); loadB(0);
    storeA(); storeB();

    for (int c = 0; c < NCH; ++c) {
        __syncthreads();
        if (c + 1 < NCH) { loadA(c + 1); loadB(c + 1); }

#pragma unroll
        for (int ks = 0; ks < 2; ++ks) {
            const int k0 = ks * 16;
            // A fragments (hi & res) for MSUB m-subtiles
            uint32_t afh[MSUB][4], afr[MSUB][4];
            const int acol = k0 + ((lane >> 4) << 3);
#pragma unroll
            for (int ms = 0; ms < MSUB; ++ms) {
                uint32_t off = (uint32_t)((wmb + ms * 16 + (lane & 15)) * ROWP + acol) * 2;
                ldm_x4(afh[ms], ahBase + off);
                ldm_x4(afr[ms], arBase + off);
            }
            // B fragments: one x4 covers two n-subtiles
            uint32_t bfh[NSUB][2], bfr[NSUB][2];
            const int bro = ((lane & 16) >> 1) + (lane & 7);
            const int bcol = k0 + (lane & 8);
#pragma unroll
            for (int np = 0; np < NSUB / 2; ++np) {
                uint32_t off = (uint32_t)((wnb + np * 16 + bro) * ROWP + bcol) * 2;
                uint32_t t4[4];
                ldm_x4(t4, bhBase + off);
                bfh[2 * np][0] = t4[0]; bfh[2 * np][1] = t4[1];
                bfh[2 * np + 1][0] = t4[2]; bfh[2 * np + 1][1] = t4[3];
                ldm_x4(t4, brBase + off);
                bfr[2 * np][0] = t4[0]; bfr[2 * np][1] = t4[1];
                bfr[2 * np + 1][0] = t4[2]; bfr[2 * np + 1][1] = t4[3];
            }
            // MMAs: hi*hi + hi*res + res*hi
#pragma unroll
            for (int ms = 0; ms < MSUB; ++ms)
#pragma unroll
                for (int ns = 0; ns < NSUB; ++ns) {
                    mma_bf16(acc[ms][ns], afh[ms], bfh[ns]);
                    mma_bf16(acc[ms][ns], afh[ms], bfr[ns]);
                    mma_bf16(acc[ms][ns], afr[ms], bfh[ns]);
                }
        }
        __syncthreads();
        if (c + 1 < NCH) { storeA(); storeB(); }
    }

    // epilogue
    const int g = lane >> 2, t = lane & 3;
#pragma unroll
    for (int ms = 0; ms < MSUB; ++ms)
#pragma unroll
        for (int ns = 0; ns < NSUB; ++ns) {
            int m = m0 + wmb + ms * 16 + g;
            int n = n0 + wnb + ns * 8 + 2 * t;
            if (m < M)
                *(float2*)(C + (size_t)m * N + n) = make_float2(acc[ms][ns][0], acc[ms][ns][1]);
            if (m + 8 < M)
                *(float2*)(C + (size_t)(m + 8) * N + n) = make_float2(acc[ms][ns][2], acc[ms][ns][3]);
        }
}

// ---------------- attention scores el/er per (node, head) ------------------
template <int H, int F>
__global__ void scores_kernel(const float* __restrict__ z,
                              const float* __restrict__ al,
                              const float* __restrict__ ar,
                              float* __restrict__ el, float* __restrict__ er,
                              int N) {
    int idx = blockIdx.x * blockDim.x + threadIdx.x;
    if (idx >= N * H) return;
    int h = idx % H;
    const float* zr = z + (size_t)idx * F;
    const float* alr = al + h * F;
    const float* arr = ar + h * F;
    float sl = 0.f, sr = 0.f;
#pragma unroll 4
    for (int f = 0; f < F; f += 4) {
        float4 zv = *(const float4*)(zr + f);
        float4 av = *(const float4*)(alr + f);
        float4 bv = *(const float4*)(arr + f);
        sl += zv.x * av.x + zv.y * av.y + zv.z * av.z + zv.w * av.w;
        sr += zv.x * bv.x + zv.y * bv.y + zv.z * bv.z + zv.w * bv.w;
    }
    el[idx] = sl;
    er[idx] = sr;
}

// ---------------- per-node edge softmax + aggregation (one warp per node) --
template <int H, int F, bool ELU>
__global__ void aggregate_kernel(const float* __restrict__ z,
                                 const int* __restrict__ src,
                                 const int* __restrict__ rowptr,
                                 const float* __restrict__ el,
                                 const float* __restrict__ er,
                                 float* __restrict__ out, int N) {
    constexpr int HFv = H * F;
    int warp_id = (blockIdx.x * blockDim.x + threadIdx.x) >> 5;
    if (warp_id >= N) return;
    int lane = threadIdx.x & 31;
    int v = warp_id;
    int start = rowptr[v];
    int end   = rowptr[v + 1];

    int h = lane % H;
    float erv = er[(size_t)v * H + h];

    float m = -INFINITY;
    for (int i = start + lane / H; i < end; i += 32 / H) {
        int s = src[i];
        float e = el[(size_t)s * H + h] + erv;
        e = e > 0.f ? e : 0.2f * e;
        m = fmaxf(m, e);
    }
#pragma unroll
    for (int off = H; off < 32; off <<= 1)
        m = fmaxf(m, __shfl_xor_sync(0xFFFFFFFFu, m, off));

    float denom = 0.f;

    if constexpr (HFv >= 64 && F == 64 && H == 8) {
        constexpr int KP = HFv / 64;
        ull acc[KP];
#pragma unroll
        for (int k = 0; k < KP; ++k) acc[k] = 0ull;

        for (int i = start; i < end; ++i) {
            int s = __shfl_sync(0xFFFFFFFFu, lane == 0 ? src[i] : 0, 0);
            float e = el[(size_t)s * H + h] + erv;
            e = e > 0.f ? e : 0.2f * e;
            float w = __expf(e - m);
            denom += w;
            const float* zr = z + (size_t)s * HFv;
#pragma unroll
            for (int k = 0; k < KP; ++k) {
                float wk = __shfl_sync(0xFFFFFFFFu, w, k);
                ull zv = *(const ull*)(zr + k * 64 + lane * 2);
                ffma2(acc[k], zv, dup_f32x2(wk));
            }
        }

        float* outr = out + (size_t)v * HFv;
#pragma unroll
        for (int k = 0; k < KP; ++k) {
            float d = __shfl_sync(0xFFFFFFFFu, denom, k);
            float2 p = unpack_f32x2(acc[k]);
            float vx = (end > start) ? p.x / d : 0.f;
            float vy = (end > start) ? p.y / d : 0.f;
            if (ELU) {
                vx = vx > 0.f ? vx : (__expf(vx) - 1.f);
                vy = vy > 0.f ? vy : (__expf(vy) - 1.f);
            }
            *(float2*)(outr + k * 64 + lane * 2) = make_float2(vx, vy);
        }
    } else {
        constexpr int KF = HFv / 32;
        float acc[KF];
#pragma unroll
        for (int k = 0; k < KF; ++k) acc[k] = 0.f;

        for (int i = start; i < end; ++i) {
            int s = __shfl_sync(0xFFFFFFFFu, lane == 0 ? src[i] : 0, 0);
            float e = el[(size_t)s * H + h] + erv;
            e = e > 0.f ? e : 0.2f * e;
            float w = __expf(e - m);
            denom += w;
            float wv[H];
#pragma unroll
            for (int hh = 0; hh < H; ++hh) wv[hh] = __shfl_sync(0xFFFFFFFFu, w, hh);
            const float* zr = z + (size_t)s * HFv;
#pragma unroll
            for (int k = 0; k < KF; ++k)
                acc[k] += wv[(k * 32) / F] * zr[k * 32 + lane];
        }

        float denv[H];
#pragma unroll
        for (int hh = 0; hh < H; ++hh) denv[hh] = __shfl_sync(0xFFFFFFFFu, denom, hh);

        float* outr = out + (size_t)v * HFv;
#pragma unroll
        for (int k = 0; k < KF; ++k) {
            float d = denv[(k * 32) / F];
            float val = (end > start) ? acc[k] / d : 0.f;
            if (ELU) val = val > 0.f ? val : (__expf(val) - 1.f);
            outr[k * 32 + lane] = val;
        }
    }
}

// ---------------- launch --------------------------------------------------
extern "C" void kernel_launch(void* const* d_in, const int* in_sizes, int n_in,
                              void* d_out, int out_size) {
    const float* h   = (const float*)d_in[0];
    const int*   src = (const int*)  d_in[1];
    const int*   dst = (const int*)  d_in[2];
    const float* W1  = (const float*)d_in[3];
    const float* al1 = (const float*)d_in[4];
    const float* ar1 = (const float*)d_in[5];
    const float* W2  = (const float*)d_in[6];
    const float* al2 = (const float*)d_in[7];
    const float* ar2 = (const float*)d_in[8];
    const float* W3  = (const float*)d_in[9];
    const float* al3 = (const float*)d_in[10];
    const float* ar3 = (const float*)d_in[11];
    float* out = (float*)d_out;

    const int N = N_NODES, E = N_EDGES;

    float *z, *x1, *x2, *el, *er;
    int* rowptr;
    cudaGetSymbolAddress((void**)&z,  g_z);
    cudaGetSymbolAddress((void**)&x1, g_x1);
    cudaGetSymbolAddress((void**)&x2, g_x2);
    cudaGetSymbolAddress((void**)&el, g_el);
    cudaGetSymbolAddress((void**)&er, g_er);
    cudaGetSymbolAddress((void**)&rowptr, g_rowptr);

    rowptr_kernel<<<(N + 1 + 255) / 256, 256>>>(dst, rowptr, E, N);

    const int mtiles = (N + 127) / 128;          // 196
    int agg_blocks = (N * 32 + 255) / 256;

    // ---- layer 1: z = h @ W1^T  [N,256] -> [N,512]
    gemm_mma_kernel<64, 4, 2><<<dim3(HF / 64, mtiles), 256>>>(h, W1, z, N, HF, IN_FEATS);
    scores_kernel<HEADS, HID><<<(N * HEADS + 255) / 256, 256>>>(z, al1, ar1, el, er, N);
    aggregate_kernel<HEADS, HID, true><<<agg_blocks, 256>>>(z, src, rowptr, el, er, x1, N);

    // ---- layer 2: z = x1 @ W2^T  [N,512] -> [N,512]
    gemm_mma_kernel<64, 4, 2><<<dim3(HF / 64, mtiles), 256>>>(x1, W2, z, N, HF, HF);
    scores_kernel<HEADS, HID><<<(N * HEADS + 255) / 256, 256>>>(z, al2, ar2, el, er, N);
    aggregate_kernel<HEADS, HID, true><<<agg_blocks, 256>>>(z, src, rowptr, el, er, x2, N);

    // ---- layer 3: z = x2 @ W3^T  [N,512] -> [N,32]
    gemm_mma_kernel<32, 8, 1><<<dim3(1, mtiles), 256>>>(x2, W3, z, N, CLASSES, HF);
    scores_kernel<1, CLASSES><<<(N + 255) / 256, 256>>>(z, al3, ar3, el, er, N);
    aggregate_kernel<1, CLASSES, false><<<agg_blocks, 256>>>(z, src, rowptr, el, er, out, N);
}